// round 16
// baseline (speedup 1.0000x reference)
#include <cuda_runtime.h>
#include <cuda_fp16.h>
#include <math_constants.h>

// Problem-shape constants (fixed by setup_inputs)
#define NN   50000
#define EN   400000
#define EEN  800000
#define CN   800000

#define FULLMASK 0xffffffffu

// ---------------- static scratch (no allocation allowed) ----------------
// q/k stored HEAD-MAJOR: g_qh[h][E][32] fp16 (64 B rows) -> per-head working
// set fits L2 during per-head attention phases.
__device__ __half  g_qh[(size_t)4 * EN * 32];
__device__ __half  g_kh[(size_t)4 * EN * 32];
__device__ float  g_vs[(size_t)4 * EN];       // vsum head-major [4][E]
__device__ float2 g_sn[(size_t)EN * 4];       // [E,4] interleaved (exp-sum, exp*vsum)
__device__ float4 g_S3[NN];                   // stage3 per-head exp-sum
__device__ float  g_whk[4];
__device__ float  g_wv[4];
// tf32 B-fragments for the projection MMA, laid out exactly per-lane:
// index = warp*1024 + nt*256 + ks*64 + r*32 + lane
__device__ unsigned int g_bfrag[8192];
__device__ float  g_bq[128];                  // b2 @ Wq
__device__ float  g_bk[128];                  // b2 @ Wk
__device__ float4 g_W2v[32];                  // W2 @ wvh  [32,4]
__device__ float4 g_bv;                       // b2 @ wvh

__device__ __forceinline__ unsigned int f2tf32(float f) {
    unsigned int r;
    asm("cvt.rna.tf32.f32 %0, %1;" : "=r"(r) : "f"(f));
    return r;
}
__device__ __forceinline__ unsigned long long pk2(float a, float b) {
    unsigned long long r;
    asm("mov.b64 %0, {%1, %2};" : "=l"(r) : "f"(a), "f"(b));
    return r;
}
__device__ __forceinline__ void ffma2(unsigned long long& d,
                                      unsigned long long a,
                                      unsigned long long b) {
    asm("fma.rn.f32x2 %0, %1, %2, %0;" : "+l"(d) : "l"(a), "l"(b));
}
__device__ __forceinline__ float2 unpk(unsigned long long v) {
    float2 r;
    asm("mov.b64 {%0, %1}, %2;" : "=f"(r.x), "=f"(r.y) : "l"(v));
    return r;
}

// ---------------- K_prep_all: weight folding + MMA fragment layout + S3 zero ----------------
__global__ void k_prep_all(const float* __restrict__ W2, const float* __restrict__ b2,
                           const float* __restrict__ Wq, const float* __restrict__ Wk,
                           const float* __restrict__ Wv,
                           const float* __restrict__ Wq2,
                           const float* __restrict__ Wk2,
                           const float* __restrict__ Wv2, int N) {
    int idx = blockIdx.x * 256 + threadIdx.x;
    if (idx < 8192) {                       // B fragments, lane-exact layout
        int lane = idx & 31;
        int r  = (idx >> 5) & 1;
        int ks = (idx >> 6) & 3;
        int nt = (idx >> 8) & 3;
        int w  = idx >> 10;
        int col = w * 32 + nt * 8 + (lane >> 2);   // 0..255 (q||k)
        int kk  = ks * 8 + (lane & 3) + r * 4;     // 0..31
        const float* Wx = (col < 128) ? Wq : Wk;
        int c = (col < 128) ? col : (col - 128);
        float s = 0.f;
        for (int m = 0; m < 128; m++) s += W2[kk * 128 + m] * Wx[m * 128 + c];
        g_bfrag[idx] = f2tf32(s);
    } else if (idx < 8320) {                // bq
        int c = idx - 8192;
        float s = 0.f;
        for (int m = 0; m < 128; m++) s += b2[m] * Wq[m * 128 + c];
        g_bq[c] = s;
    } else if (idx < 8448) {                // bk
        int c = idx - 8320;
        float s = 0.f;
        for (int m = 0; m < 128; m++) s += b2[m] * Wk[m * 128 + c];
        g_bk[c] = s;
    } else if (idx < 8576) {                // W2v [32][4] (wvh recomputed inline)
        int i = idx - 8448;
        int r = i >> 2, hh = i & 3;
        float s = 0.f;
        for (int m = 0; m < 128; m++) {
            float w = 0.f;
            for (int d = 0; d < 32; d++) w += Wv[m * 128 + hh * 32 + d];
            s += W2[r * 128 + m] * w;
        }
        ((float*)&g_W2v[r])[hh] = s;
    } else if (idx < 8580) {                // bv
        int hh = idx - 8576;
        float s = 0.f;
        for (int m = 0; m < 128; m++) {
            float w = 0.f;
            for (int d = 0; d < 32; d++) w += Wv[m * 128 + hh * 32 + d];
            s += b2[m] * w;
        }
        ((float*)&g_bv)[hh] = s;
    } else if (idx < 8584) {                // whk
        int h = idx - 8580;
        float qk = 0.f;
        for (int d = 0; d < 32; d++) qk += Wq2[h * 32 + d] * Wk2[h * 32 + d];
        g_whk[h] = qk * 0.17677669529663687f;   // 1/sqrt(32)
    } else if (idx < 8588) {                // wv
        int h = idx - 8584;
        float vv = 0.f;
        for (int d = 0; d < 32; d++) vv += Wv2[h * 32 + d];
        g_wv[h] = vv;
    } else {                                // zero g_S3 (consumed by k_edge atomics)
        int j = idx - 8704;
        if (j >= 0 && j < N)
            g_S3[j] = make_float4(0.f, 0.f, 0.f, 0.f);
    }
}

// ---------------- K1: edge MLP + tensor-core (tf32 mma) q/k projection ----------------
// Block = 256 threads = 8 warps, 64 edges (E = 6250 * 64 exactly).
// Phase A: layer-1 z in exact fp32 via transposed-ea SMEM + packed FFMA2
//          (edge pairs), vsum via SMEM per-lane dot (lane = edge x head).
// Phase B: block GEMM [64x32] @ [32x256 (q||k)] via mma.sync.m16n8k8.tf32;
//          warp w owns head w (q, w<4) or head w-4 (k); stores head-major.
// Prologue: zero g_sn/out + full stage-3 S3 accumulation (independent work).
#define ZSTR 36
#define EASTR 10
#define ZSSTR 33
__global__ void __launch_bounds__(256) k_edge(
    const float* __restrict__ x, const int* __restrict__ ei,
    const float* __restrict__ ea,
    const float* __restrict__ W1, const float* __restrict__ b1,
    const int* __restrict__ nni,
    float* __restrict__ out, int N, int E, int C)
{
    __shared__ float  W1s[34 * 32];            // 4352 B
    __shared__ float  b1s[32];                 //  128 B
    __shared__ unsigned int zt[64 * ZSTR];     // 9216 B  tf32 z (for MMA A frags)
    __shared__ float  zs[8 * 8 * ZSSTR];       // 8448 B  fp32 z (for vsum dots)
    __shared__ float  eat[8 * 32 * EASTR];     // 10240 B transposed ea per warp
    __shared__ float  bqk[256];                // 1024 B
    __shared__ float4 W2vs[32];                //  512 B
    __shared__ float4 bvs;                     //   16 B

    int tid = threadIdx.x;

    // ---- folded zero-init + stage-3 S3 accumulation ----
    {
        int g = blockIdx.x * 256 + tid;
        const float4 z4 = make_float4(0.f, 0.f, 0.f, 0.f);
        if (g < E) {
            ((float4*)g_sn)[2 * g + 0] = z4;
            ((float4*)g_sn)[2 * g + 1] = z4;
        }
        if (g < N) out[g] = 0.f;
        if (g < C) {
            int ns = nni[g], nd = nni[C + g];
            float s = __ldg(x + ns) * __ldg(x + nd);
            float4 ev;
            ev.x = __expf(s * g_whk[0]);
            ev.y = __expf(s * g_whk[1]);
            ev.z = __expf(s * g_whk[2]);
            ev.w = __expf(s * g_whk[3]);
            atomicAdd(&g_S3[nd], ev);
        }
    }

    // ---- SMEM fills (small) ----
    for (int i = tid; i < 34 * 32; i += 256) W1s[i] = W1[i];
    if (tid < 32) b1s[tid] = b1[tid];
    bqk[tid] = (tid < 128) ? g_bq[tid] : g_bk[tid - 128];
    if (tid < 32) W2vs[tid] = g_W2v[tid];
    if (tid == 0) bvs = g_bv;

    int lane = tid & 31;
    int warp = tid >> 5;
    int e0w = blockIdx.x * 64 + warp * 8;   // this warp's 8 edges

    // ---- gather endpoint x values: lanes 0-7 -> xs, lanes 8-15 -> xd ----
    float xv = 0.f;
    if (lane < 16) {
        int e = e0w + (lane & 7);
        int idx = (lane < 8) ? ei[e] : ei[E + e];
        xv = __ldg(x + idx);
    }

    // ---- stage ea transposed: eat[m][edge] (per-warp tile) ----
    {
        float* eatw = eat + warp * 32 * EASTR;
        const float4* ea4 = (const float4*)(ea + (size_t)e0w * 32);
        #pragma unroll
        for (int r = 0; r < 2; r++) {
            float4 v = __ldg(ea4 + r * 32 + lane);
            int j  = r * 4 + (lane >> 3);
            int m0 = (lane & 7) * 4;
            eatw[(m0 + 0) * EASTR + j] = v.x;
            eatw[(m0 + 1) * EASTR + j] = v.y;
            eatw[(m0 + 2) * EASTR + j] = v.z;
            eatw[(m0 + 3) * EASTR + j] = v.w;
        }
    }
    __syncthreads();

    // ---- Phase A: layer 1, packed over edge pairs (exact fp32 per lane) ----
    {
        float bb = b1s[lane];
        unsigned long long wr0 = pk2(W1s[lane], W1s[lane]);
        unsigned long long wr1 = pk2(W1s[32 + lane], W1s[32 + lane]);
        unsigned long long acc2[4];
        #pragma unroll
        for (int p = 0; p < 4; p++) {
            float xs0 = __shfl_sync(FULLMASK, xv, 2 * p);
            float xs1 = __shfl_sync(FULLMASK, xv, 2 * p + 1);
            float xd0 = __shfl_sync(FULLMASK, xv, 8 + 2 * p);
            float xd1 = __shfl_sync(FULLMASK, xv, 9 + 2 * p);
            acc2[p] = pk2(bb, bb);
            ffma2(acc2[p], wr0, pk2(xs0, xs1));
            ffma2(acc2[p], wr1, pk2(xd0, xd1));
        }
        const float* eatw = eat + warp * 32 * EASTR;
        #pragma unroll 8
        for (int m = 0; m < 32; m++) {
            float w = W1s[(2 + m) * 32 + lane];
            unsigned long long wp = pk2(w, w);
            const float* row = eatw + m * EASTR;
            #pragma unroll
            for (int p = 0; p < 4; p++) {
                float2 ep = *(const float2*)(row + 2 * p);
                ffma2(acc2[p], wp, pk2(ep.x, ep.y));
            }
        }
        float* zsw = zs + warp * 8 * ZSSTR;
        unsigned int* ztw = zt + warp * 8 * ZSTR;
        #pragma unroll
        for (int p = 0; p < 4; p++) {
            float2 zz = unpk(acc2[p]);
            float z0 = fmaxf(zz.x, 0.f);
            float z1 = fmaxf(zz.y, 0.f);
            zsw[(2 * p) * ZSSTR + lane] = z0;
            zsw[(2 * p + 1) * ZSSTR + lane] = z1;
            ztw[(2 * p) * ZSTR + lane] = f2tf32(z0);
            ztw[(2 * p + 1) * ZSTR + lane] = f2tf32(z1);
        }
    }
    __syncwarp();

    // ---- vsum: lane = (edge e = lane>>2, head h = lane&3), serial fp32 dot ----
    // stored head-major: g_vs[h][E]
    {
        int e = lane >> 2, h = lane & 3;
        const float* zsw = zs + warp * 8 * ZSSTR + e * ZSSTR;
        const float* wv = (const float*)W2vs;
        float acc = ((const float*)&bvs)[h];
        #pragma unroll 8
        for (int m = 0; m < 32; m++)
            acc = fmaf(zsw[m], wv[m * 4 + h], acc);
        g_vs[(size_t)h * EN + e0w + e] = acc;
    }

    // ---- preload B fragments (after Phase A: keeps Phase-A regs low) ----
    unsigned int bf[4][4][2];
    #pragma unroll
    for (int nt = 0; nt < 4; nt++)
        #pragma unroll
        for (int ks = 0; ks < 4; ks++)
            #pragma unroll
            for (int r = 0; r < 2; r++)
                bf[nt][ks][r] = __ldg(g_bfrag + warp * 1024 + nt * 256 + ks * 64 + r * 32 + lane);

    __syncthreads();   // all zt written

    // ---- Phase B: tf32 mma projection; store head-major 64 B rows ----
    {
        int g = lane >> 2, t = lane & 3;
        int wslice = warp * 32;
        __half* basep = (warp < 4) ? (g_qh + (size_t)warp * EN * 32)
                                   : (g_kh + (size_t)(warp - 4) * EN * 32);
        int e0blk = blockIdx.x * 64;

        #pragma unroll
        for (int mt = 0; mt < 4; mt++) {
            unsigned int af[4][4];
            #pragma unroll
            for (int ks = 0; ks < 4; ks++) {
                int r0 = mt * 16 + g, kk = ks * 8 + t;
                af[ks][0] = zt[r0 * ZSTR + kk];
                af[ks][1] = zt[(r0 + 8) * ZSTR + kk];
                af[ks][2] = zt[r0 * ZSTR + kk + 4];
                af[ks][3] = zt[(r0 + 8) * ZSTR + kk + 4];
            }
            #pragma unroll
            for (int nt = 0; nt < 4; nt++) {
                float c0 = 0.f, c1 = 0.f, c2 = 0.f, c3 = 0.f;
                #pragma unroll
                for (int ks = 0; ks < 4; ks++) {
                    asm volatile(
                        "mma.sync.aligned.m16n8k8.row.col.f32.tf32.tf32.f32 "
                        "{%0,%1,%2,%3}, {%4,%5,%6,%7}, {%8,%9}, {%0,%1,%2,%3};"
                        : "+f"(c0), "+f"(c1), "+f"(c2), "+f"(c3)
                        : "r"(af[ks][0]), "r"(af[ks][1]), "r"(af[ks][2]), "r"(af[ks][3]),
                          "r"(bf[nt][ks][0]), "r"(bf[nt][ks][1]));
                }
                int col = wslice + nt * 8 + 2 * t;
                float2 bia = *(const float2*)(bqk + col);
                c0 += bia.x; c1 += bia.y; c2 += bia.x; c3 += bia.y;
                __half2 h01 = __floats2half2_rn(c0, c1);
                __half2 h23 = __floats2half2_rn(c2, c3);
                int lcol = nt * 8 + 2 * t;          // col within head (0..31)
                int er0 = e0blk + mt * 16 + g;
                *(__half2*)(basep + (size_t)er0 * 32 + lcol) = h01;
                *(__half2*)(basep + (size_t)(er0 + 8) * 32 + lcol) = h23;
            }
        }
    }
}

// ---------------- K2: per-head attention (L2-resident phases) ----------------
// Warp handles 4 pairs of ONE head: octet (8 lanes) per pair, 64 B q + 64 B k
// gathers, fp32 dot, octet reduce, vector float2 atomic. Heads processed in
// grid order -> per-head working set (~72 MB) stays L2-resident.
#define APW 4
__global__ void __launch_bounds__(256) k_attn(const int* __restrict__ eei, int EE) {
    int gw = (blockIdx.x * 256 + threadIdx.x) >> 5;
    int lane = threadIdx.x & 31;
    int wph = EE / APW;                  // warps per head (EE divisible by 4)
    int h = gw / wph;
    if (h >= 4) return;
    int b = (gw - h * wph) * APW;

    // lanes 0-3: es for pairs 0..3; lanes 4-7: ed
    int li = 0;
    if (lane < 4)      li = __ldg(eei + b + lane);
    else if (lane < 8) li = __ldg(eei + EE + b + lane - 4);

    int p = lane >> 3;                   // pair index (octet)
    int sub = lane & 7;
    int es_p = __shfl_sync(FULLMASK, li, p);
    int ed_p = __shfl_sync(FULLMASK, li, 4 + p);

    const uint2* qrow = (const uint2*)(g_qh + ((size_t)h * EN + ed_p) * 32);
    const uint2* krow = (const uint2*)(g_kh + ((size_t)h * EN + es_p) * 32);
    uint2 qu = __ldg(qrow + sub);
    uint2 ku = __ldg(krow + sub);

    float2 q0 = __half22float2(*(__half2*)&qu.x);
    float2 q1 = __half22float2(*(__half2*)&qu.y);
    float2 k0 = __half22float2(*(__half2*)&ku.x);
    float2 k1 = __half22float2(*(__half2*)&ku.y);
    float d = q0.x * k0.x + q0.y * k0.y + q1.x * k1.x + q1.y * k1.y;
    d += __shfl_xor_sync(FULLMASK, d, 1);
    d += __shfl_xor_sync(FULLMASK, d, 2);
    d += __shfl_xor_sync(FULLMASK, d, 4);

    if (sub == 0) {
        float ex = __expf(d * 0.17677669529663687f);
        float v = __ldg(g_vs + (size_t)h * EN + es_p);
        atomicAdd(&g_sn[(size_t)ed_p * 4 + h], make_float2(ex, ex * v));
    }
}

// ---------------- K3: uef + stage3 messages (merged final pass) ----------------
__global__ void k_n3(float* __restrict__ out, const float* __restrict__ x,
                     const int* __restrict__ nni, int N, int E, int C) {
    int c = blockIdx.x * blockDim.x + threadIdx.x;
    if (c < E) {
        float4 a = ((const float4*)g_sn)[2 * c + 0];
        float4 b = ((const float4*)g_sn)[2 * c + 1];
        float u = a.y / (a.x + 1e-16f) + a.w / (a.z + 1e-16f)
                + b.y / (b.x + 1e-16f) + b.w / (b.z + 1e-16f);
        out[N + c] = u * (1.f / 128.f);
    }
    if (c < C) {
        int ns = nni[c], nd = nni[C + c];
        float xs = __ldg(x + ns);
        float s = xs * __ldg(x + nd);
        float4 S = g_S3[nd];
        const float* Sf = (const float*)&S;
        float acc = 0.f;
        #pragma unroll
        for (int h = 0; h < 4; h++) {
            float al = __expf(s * g_whk[h]) / (Sf[h] + 1e-16f);
            acc = fmaf(al, g_wv[h], acc);
        }
        atomicAdd(&out[nd], acc * xs * (1.f / 128.f));
    }
}

// ---------------- launch ----------------
extern "C" void kernel_launch(void* const* d_in, const int* in_sizes, int n_in,
                              void* d_out, int out_size) {
    const float* x   = (const float*)d_in[0];
    const int*   ei  = (const int*)d_in[1];
    const float* ea  = (const float*)d_in[2];
    const int*   eei = (const int*)d_in[3];
    const int*   nni = (const int*)d_in[4];
    const float* W1  = (const float*)d_in[5];
    const float* b1  = (const float*)d_in[6];
    const float* W2  = (const float*)d_in[7];
    const float* b2  = (const float*)d_in[8];
    const float* Wq  = (const float*)d_in[9];
    const float* Wk  = (const float*)d_in[10];
    const float* Wv  = (const float*)d_in[11];
    const float* Wq2 = (const float*)d_in[12];
    const float* Wk2 = (const float*)d_in[13];
    const float* Wv2 = (const float*)d_in[14];
    float* out = (float*)d_out;

    int N  = in_sizes[0];
    int E  = in_sizes[1] / 2;
    int EE = in_sizes[3] / 2;
    int C  = in_sizes[4] / 2;

    k_prep_all<<<(8704 + N + 255) / 256, 256>>>(W2, b2, Wq, Wk, Wv, Wq2, Wk2, Wv2, N);
    k_edge<<<(E + 63) / 64, 256>>>(x, ei, ea, W1, b1, nni, out, N, E, C);
    // total warps = 4 heads * (EE/APW); 8 warps per block
    int attn_blocks = (4 * (EE / APW) + 7) / 8;
    k_attn<<<attn_blocks, 256>>>(eei, EE);
    k_n3<<<(C + 255) / 256, 256>>>(out, x, nni, N, E, C);
}

// round 17
// speedup vs baseline: 1.1695x; 1.1695x over previous
#include <cuda_runtime.h>
#include <cuda_fp16.h>
#include <math_constants.h>

// Problem-shape constants (fixed by setup_inputs)
#define NN   50000
#define EN   400000
#define EEN  800000
#define CN   800000

#define FULLMASK 0xffffffffu

// ---------------- static scratch (no allocation allowed) ----------------
__device__ __half  g_qh[(size_t)EN * 128];    // [E,128] q projection (fp16 storage)
__device__ __half  g_kh[(size_t)EN * 128];    // [E,128] k projection (fp16 storage)
__device__ float4 g_vsum[EN];                 // [E,4]  per-head summed v
__device__ float2 g_sn[(size_t)EN * 4];       // [E,4] interleaved (exp-sum, exp*vsum)
__device__ float4 g_S3[NN];                   // stage3 per-head exp-sum
__device__ float  g_whk[4];
__device__ float  g_wv[4];
// tf32 B-fragments for the projection MMA, laid out exactly per-lane:
// index = warp*1024 + nt*256 + ks*64 + r*32 + lane
__device__ unsigned int g_bfrag[8192];
__device__ float  g_bq[128];                  // b2 @ Wq
__device__ float  g_bk[128];                  // b2 @ Wk
__device__ float4 g_W2v[32];                  // W2 @ wvh  [32,4]
__device__ float4 g_bv;                       // b2 @ wvh

__device__ __forceinline__ unsigned int f2tf32(float f) {
    unsigned int r;
    asm("cvt.rna.tf32.f32 %0, %1;" : "=r"(r) : "f"(f));
    return r;
}
__device__ __forceinline__ unsigned long long pk2(float a, float b) {
    unsigned long long r;
    asm("mov.b64 %0, {%1, %2};" : "=l"(r) : "f"(a), "f"(b));
    return r;
}
__device__ __forceinline__ void ffma2(unsigned long long& d,
                                      unsigned long long a,
                                      unsigned long long b) {
    asm("fma.rn.f32x2 %0, %1, %2, %0;" : "+l"(d) : "l"(a), "l"(b));
}
__device__ __forceinline__ float2 unpk(unsigned long long v) {
    float2 r;
    asm("mov.b64 {%0, %1}, %2;" : "=f"(r.x), "=f"(r.y) : "l"(v));
    return r;
}

// ---------------- K_prep_all: weight folding + MMA fragment layout + S3 zero ----------------
__global__ void k_prep_all(const float* __restrict__ W2, const float* __restrict__ b2,
                           const float* __restrict__ Wq, const float* __restrict__ Wk,
                           const float* __restrict__ Wv,
                           const float* __restrict__ Wq2,
                           const float* __restrict__ Wk2,
                           const float* __restrict__ Wv2, int N) {
    int idx = blockIdx.x * 256 + threadIdx.x;
    if (idx < 8192) {                       // B fragments, lane-exact layout
        int lane = idx & 31;
        int r  = (idx >> 5) & 1;
        int ks = (idx >> 6) & 3;
        int nt = (idx >> 8) & 3;
        int w  = idx >> 10;
        int col = w * 32 + nt * 8 + (lane >> 2);   // 0..255 (q||k)
        int kk  = ks * 8 + (lane & 3) + r * 4;     // 0..31
        const float* Wx = (col < 128) ? Wq : Wk;
        int c = (col < 128) ? col : (col - 128);
        float s = 0.f;
        for (int m = 0; m < 128; m++) s += W2[kk * 128 + m] * Wx[m * 128 + c];
        g_bfrag[idx] = f2tf32(s);
    } else if (idx < 8320) {                // bq
        int c = idx - 8192;
        float s = 0.f;
        for (int m = 0; m < 128; m++) s += b2[m] * Wq[m * 128 + c];
        g_bq[c] = s;
    } else if (idx < 8448) {                // bk
        int c = idx - 8320;
        float s = 0.f;
        for (int m = 0; m < 128; m++) s += b2[m] * Wk[m * 128 + c];
        g_bk[c] = s;
    } else if (idx < 8576) {                // W2v [32][4] (wvh recomputed inline)
        int i = idx - 8448;
        int r = i >> 2, hh = i & 3;
        float s = 0.f;
        for (int m = 0; m < 128; m++) {
            float w = 0.f;
            for (int d = 0; d < 32; d++) w += Wv[m * 128 + hh * 32 + d];
            s += W2[r * 128 + m] * w;
        }
        ((float*)&g_W2v[r])[hh] = s;
    } else if (idx < 8580) {                // bv
        int hh = idx - 8576;
        float s = 0.f;
        for (int m = 0; m < 128; m++) {
            float w = 0.f;
            for (int d = 0; d < 32; d++) w += Wv[m * 128 + hh * 32 + d];
            s += b2[m] * w;
        }
        ((float*)&g_bv)[hh] = s;
    } else if (idx < 8584) {                // whk
        int h = idx - 8580;
        float qk = 0.f;
        for (int d = 0; d < 32; d++) qk += Wq2[h * 32 + d] * Wk2[h * 32 + d];
        g_whk[h] = qk * 0.17677669529663687f;   // 1/sqrt(32)
    } else if (idx < 8588) {                // wv
        int h = idx - 8584;
        float vv = 0.f;
        for (int d = 0; d < 32; d++) vv += Wv2[h * 32 + d];
        g_wv[h] = vv;
    } else {                                // zero g_S3 (consumed by k_edge atomics)
        int j = idx - 8704;
        if (j >= 0 && j < N)
            g_S3[j] = make_float4(0.f, 0.f, 0.f, 0.f);
    }
}

// ---------------- K1: edge MLP + tensor-core (tf32 mma) q/k projection ----------------
// Block = 256 threads = 8 warps, 64 edges (E = 6250 * 64 exactly).
// Phase A: layer-1 z in exact fp32 via transposed-ea SMEM + packed FFMA2
//          (edge pairs), vsum via SMEM per-lane dot (lane = edge x head).
// Phase B: block GEMM [64x32] @ [32x256 (q||k)] via mma.sync.m16n8k8.tf32;
//          B fragments pre-laid in g_bfrag (loaded after Phase A: low regs).
// Prologue: zero g_sn/out + full stage-3 S3 accumulation (independent work).
#define ZSTR 36
#define EASTR 10
#define ZSSTR 33
__global__ void __launch_bounds__(256) k_edge(
    const float* __restrict__ x, const int* __restrict__ ei,
    const float* __restrict__ ea,
    const float* __restrict__ W1, const float* __restrict__ b1,
    const int* __restrict__ nni,
    float* __restrict__ out, int N, int E, int C)
{
    __shared__ float  W1s[34 * 32];            // 4352 B
    __shared__ float  b1s[32];                 //  128 B
    __shared__ unsigned int zt[64 * ZSTR];     // 9216 B  tf32 z (for MMA A frags)
    __shared__ float  zs[8 * 8 * ZSSTR];       // 8448 B  fp32 z (for vsum dots)
    __shared__ float  eat[8 * 32 * EASTR];     // 10240 B transposed ea per warp
    __shared__ float  bqk[256];                // 1024 B
    __shared__ float4 W2vs[32];                //  512 B
    __shared__ float4 bvs;                     //   16 B

    int tid = threadIdx.x;

    // ---- folded zero-init + stage-3 S3 accumulation ----
    {
        int g = blockIdx.x * 256 + tid;
        const float4 z4 = make_float4(0.f, 0.f, 0.f, 0.f);
        if (g < E) {
            ((float4*)g_sn)[2 * g + 0] = z4;
            ((float4*)g_sn)[2 * g + 1] = z4;
        }
        if (g < N) out[g] = 0.f;
        if (g < C) {
            int ns = nni[g], nd = nni[C + g];
            float s = __ldg(x + ns) * __ldg(x + nd);
            float4 ev;
            ev.x = __expf(s * g_whk[0]);
            ev.y = __expf(s * g_whk[1]);
            ev.z = __expf(s * g_whk[2]);
            ev.w = __expf(s * g_whk[3]);
            atomicAdd(&g_S3[nd], ev);
        }
    }

    // ---- SMEM fills (small) ----
    for (int i = tid; i < 34 * 32; i += 256) W1s[i] = W1[i];
    if (tid < 32) b1s[tid] = b1[tid];
    bqk[tid] = (tid < 128) ? g_bq[tid] : g_bk[tid - 128];
    if (tid < 32) W2vs[tid] = g_W2v[tid];
    if (tid == 0) bvs = g_bv;

    int lane = tid & 31;
    int warp = tid >> 5;
    int e0w = blockIdx.x * 64 + warp * 8;   // this warp's 8 edges

    // ---- gather endpoint x values: lanes 0-7 -> xs, lanes 8-15 -> xd ----
    float xv = 0.f;
    if (lane < 16) {
        int e = e0w + (lane & 7);
        int idx = (lane < 8) ? ei[e] : ei[E + e];
        xv = __ldg(x + idx);
    }

    // ---- stage ea transposed: eat[m][edge] (per-warp tile) ----
    {
        float* eatw = eat + warp * 32 * EASTR;
        const float4* ea4 = (const float4*)(ea + (size_t)e0w * 32);
        #pragma unroll
        for (int r = 0; r < 2; r++) {
            float4 v = __ldg(ea4 + r * 32 + lane);
            int j  = r * 4 + (lane >> 3);
            int m0 = (lane & 7) * 4;
            eatw[(m0 + 0) * EASTR + j] = v.x;
            eatw[(m0 + 1) * EASTR + j] = v.y;
            eatw[(m0 + 2) * EASTR + j] = v.z;
            eatw[(m0 + 3) * EASTR + j] = v.w;
        }
    }
    __syncthreads();

    // ---- Phase A: layer 1, packed over edge pairs (exact fp32 per lane) ----
    {
        float bb = b1s[lane];
        unsigned long long wr0 = pk2(W1s[lane], W1s[lane]);
        unsigned long long wr1 = pk2(W1s[32 + lane], W1s[32 + lane]);
        unsigned long long acc2[4];
        #pragma unroll
        for (int p = 0; p < 4; p++) {
            float xs0 = __shfl_sync(FULLMASK, xv, 2 * p);
            float xs1 = __shfl_sync(FULLMASK, xv, 2 * p + 1);
            float xd0 = __shfl_sync(FULLMASK, xv, 8 + 2 * p);
            float xd1 = __shfl_sync(FULLMASK, xv, 9 + 2 * p);
            acc2[p] = pk2(bb, bb);
            ffma2(acc2[p], wr0, pk2(xs0, xs1));
            ffma2(acc2[p], wr1, pk2(xd0, xd1));
        }
        const float* eatw = eat + warp * 32 * EASTR;
        #pragma unroll 8
        for (int m = 0; m < 32; m++) {
            float w = W1s[(2 + m) * 32 + lane];
            unsigned long long wp = pk2(w, w);
            const float* row = eatw + m * EASTR;
            #pragma unroll
            for (int p = 0; p < 4; p++) {
                float2 ep = *(const float2*)(row + 2 * p);
                ffma2(acc2[p], wp, pk2(ep.x, ep.y));
            }
        }
        float* zsw = zs + warp * 8 * ZSSTR;
        unsigned int* ztw = zt + warp * 8 * ZSTR;
        #pragma unroll
        for (int p = 0; p < 4; p++) {
            float2 zz = unpk(acc2[p]);
            float z0 = fmaxf(zz.x, 0.f);
            float z1 = fmaxf(zz.y, 0.f);
            zsw[(2 * p) * ZSSTR + lane] = z0;
            zsw[(2 * p + 1) * ZSSTR + lane] = z1;
            ztw[(2 * p) * ZSTR + lane] = f2tf32(z0);
            ztw[(2 * p + 1) * ZSTR + lane] = f2tf32(z1);
        }
    }
    __syncwarp();

    // ---- vsum: lane = (edge e = lane>>2, head h = lane&3), serial fp32 dot ----
    {
        int e = lane >> 2, h = lane & 3;
        const float* zsw = zs + warp * 8 * ZSSTR + e * ZSSTR;
        const float* wv = (const float*)W2vs;
        float acc = ((const float*)&bvs)[h];
        #pragma unroll 8
        for (int m = 0; m < 32; m++)
            acc = fmaf(zsw[m], wv[m * 4 + h], acc);
        ((float*)g_vsum)[(size_t)(e0w + e) * 4 + h] = acc;
    }

    // ---- preload B fragments (after Phase A: keeps Phase-A regs low) ----
    unsigned int bf[4][4][2];
    #pragma unroll
    for (int nt = 0; nt < 4; nt++)
        #pragma unroll
        for (int ks = 0; ks < 4; ks++)
            #pragma unroll
            for (int r = 0; r < 2; r++)
                bf[nt][ks][r] = __ldg(g_bfrag + warp * 1024 + nt * 256 + ks * 64 + r * 32 + lane);

    __syncthreads();   // all zt written

    // ---- Phase B: tf32 mma projection. warp owns 32 cols of q||k ----
    {
        int g = lane >> 2, t = lane & 3;
        int wslice = warp * 32;
        __half* base = (warp < 4) ? g_qh : g_kh;
        int cbase = (warp < 4) ? wslice : (wslice - 128);
        int e0blk = blockIdx.x * 64;

        #pragma unroll
        for (int mt = 0; mt < 4; mt++) {
            unsigned int af[4][4];
            #pragma unroll
            for (int ks = 0; ks < 4; ks++) {
                int r0 = mt * 16 + g, kk = ks * 8 + t;
                af[ks][0] = zt[r0 * ZSTR + kk];
                af[ks][1] = zt[(r0 + 8) * ZSTR + kk];
                af[ks][2] = zt[r0 * ZSTR + kk + 4];
                af[ks][3] = zt[(r0 + 8) * ZSTR + kk + 4];
            }
            #pragma unroll
            for (int nt = 0; nt < 4; nt++) {
                float c0 = 0.f, c1 = 0.f, c2 = 0.f, c3 = 0.f;
                #pragma unroll
                for (int ks = 0; ks < 4; ks++) {
                    asm volatile(
                        "mma.sync.aligned.m16n8k8.row.col.f32.tf32.tf32.f32 "
                        "{%0,%1,%2,%3}, {%4,%5,%6,%7}, {%8,%9}, {%0,%1,%2,%3};"
                        : "+f"(c0), "+f"(c1), "+f"(c2), "+f"(c3)
                        : "r"(af[ks][0]), "r"(af[ks][1]), "r"(af[ks][2]), "r"(af[ks][3]),
                          "r"(bf[nt][ks][0]), "r"(bf[nt][ks][1]));
                }
                int col = wslice + nt * 8 + 2 * t;
                float2 bia = *(const float2*)(bqk + col);
                c0 += bia.x; c1 += bia.y; c2 += bia.x; c3 += bia.y;
                __half2 h01 = __floats2half2_rn(c0, c1);
                __half2 h23 = __floats2half2_rn(c2, c3);
                int lcol = cbase + nt * 8 + 2 * t;
                int er0 = e0blk + mt * 16 + g;
                *(__half2*)(base + (size_t)er0 * 128 + lcol) = h01;
                *(__half2*)(base + (size_t)(er0 + 8) * 128 + lcol) = h23;
            }
        }
    }
}

// ---------------- K2: fused logits + exp + segment accumulation ----------------
// Batch of 8 pairs per warp staged via cp.async (LDGSTS): 8x16B in flight
// per lane with zero register cost -> latency hidden without occupancy loss.
// Lanes 0-15 fill the q row (from ed), lanes 16-31 the k row (from es).
// Compute identical to R11: conflict-free LDS.64 + octet reduce + f2 atomic.
#define BATCH 8
__global__ void __launch_bounds__(256) k_attn(const int* __restrict__ eei, int EE) {
    __shared__ __align__(16) __half buf[8][BATCH][256];  // [warp][pair][q128|k128]

    int tid = threadIdx.x;
    int lane = tid & 31;
    int warp = tid >> 5;
    int gwarp = blockIdx.x * 8 + warp;
    int b = gwarp * BATCH;
    if (b >= EE) return;

    // indices: lanes 0-7 -> es[p], lanes 8-15 -> ed[p]
    int li = 0;
    if (lane < 8)       li = __ldg(eei + b + lane);
    else if (lane < 16) li = __ldg(eei + EE + b + lane - 8);

    int is_k = lane >> 4;          // 0: fill q (needs ed), 1: fill k (needs es)
    int sub = lane & 15;           // 16-B chunk within the 256-B row
    #pragma unroll
    for (int p = 0; p < BATCH; p++) {
        int idx = __shfl_sync(FULLMASK, li, is_k ? p : (8 + p));
        const __half* src = (is_k ? g_kh : g_qh) + (size_t)idx * 128 + sub * 8;
        unsigned du = (unsigned)__cvta_generic_to_shared(
            &buf[warp][p][is_k * 128 + sub * 8]);
        asm volatile("cp.async.cg.shared.global [%0], [%1], 16;"
                     :: "r"(du), "l"(src));
    }
    asm volatile("cp.async.commit_group;");
    asm volatile("cp.async.wait_group 0;" ::: "memory");
    __syncwarp();

    #pragma unroll
    for (int p = 0; p < BATCH; p++) {
        int es_p = __shfl_sync(FULLMASK, li, p);
        int ed_p = __shfl_sync(FULLMASK, li, 8 + p);
        const __half2* q2 = (const __half2*)&buf[warp][p][0];
        const __half2* k2 = (const __half2*)&buf[warp][p][128];
        float2 q0 = __half22float2(q2[2 * lane]);
        float2 q1 = __half22float2(q2[2 * lane + 1]);
        float2 k0 = __half22float2(k2[2 * lane]);
        float2 k1 = __half22float2(k2[2 * lane + 1]);
        float d = q0.x * k0.x + q0.y * k0.y + q1.x * k1.x + q1.y * k1.y;
        d += __shfl_xor_sync(FULLMASK, d, 1);
        d += __shfl_xor_sync(FULLMASK, d, 2);
        d += __shfl_xor_sync(FULLMASK, d, 4);
        if ((lane & 7) == 0) {
            int h = lane >> 3;
            float ex = __expf(d * 0.17677669529663687f);
            float v = ((const float*)g_vsum)[(size_t)es_p * 4 + h];
            atomicAdd(&g_sn[(size_t)ed_p * 4 + h], make_float2(ex, ex * v));
        }
    }
}

// ---------------- K3: uef + stage3 messages (merged final pass) ----------------
__global__ void k_n3(float* __restrict__ out, const float* __restrict__ x,
                     const int* __restrict__ nni, int N, int E, int C) {
    int c = blockIdx.x * blockDim.x + threadIdx.x;
    if (c < E) {
        float4 a = ((const float4*)g_sn)[2 * c + 0];
        float4 b = ((const float4*)g_sn)[2 * c + 1];
        float u = a.y / (a.x + 1e-16f) + a.w / (a.z + 1e-16f)
                + b.y / (b.x + 1e-16f) + b.w / (b.z + 1e-16f);
        out[N + c] = u * (1.f / 128.f);
    }
    if (c < C) {
        int ns = nni[c], nd = nni[C + c];
        float xs = __ldg(x + ns);
        float s = xs * __ldg(x + nd);
        float4 S = g_S3[nd];
        const float* Sf = (const float*)&S;
        float acc = 0.f;
        #pragma unroll
        for (int h = 0; h < 4; h++) {
            float al = __expf(s * g_whk[h]) / (Sf[h] + 1e-16f);
            acc = fmaf(al, g_wv[h], acc);
        }
        atomicAdd(&out[nd], acc * xs * (1.f / 128.f));
    }
}

// ---------------- launch ----------------
extern "C" void kernel_launch(void* const* d_in, const int* in_sizes, int n_in,
                              void* d_out, int out_size) {
    const float* x   = (const float*)d_in[0];
    const int*   ei  = (const int*)d_in[1];
    const float* ea  = (const float*)d_in[2];
    const int*   eei = (const int*)d_in[3];
    const int*   nni = (const int*)d_in[4];
    const float* W1  = (const float*)d_in[5];
    const float* b1  = (const float*)d_in[6];
    const float* W2  = (const float*)d_in[7];
    const float* b2  = (const float*)d_in[8];
    const float* Wq  = (const float*)d_in[9];
    const float* Wk  = (const float*)d_in[10];
    const float* Wv  = (const float*)d_in[11];
    const float* Wq2 = (const float*)d_in[12];
    const float* Wk2 = (const float*)d_in[13];
    const float* Wv2 = (const float*)d_in[14];
    float* out = (float*)d_out;

    int N  = in_sizes[0];
    int E  = in_sizes[1] / 2;
    int EE = in_sizes[3] / 2;
    int C  = in_sizes[4] / 2;

    k_prep_all<<<(8704 + N + 255) / 256, 256>>>(W2, b2, Wq, Wk, Wv, Wq2, Wk2, Wv2, N);
    k_edge<<<(E + 63) / 64, 256>>>(x, ei, ea, W1, b1, nni, out, N, E, C);
    k_attn<<<(EE / BATCH + 7) / 8, 256>>>(eei, EE);
    k_n3<<<(C + 255) / 256, 256>>>(out, x, nni, N, E, C);
}